// round 1
// baseline (speedup 1.0000x reference)
#include <cuda_runtime.h>

#define BSZ   8
#define NROI  64
#define HDIM  512
#define NLAYER 5
#define BI    (BSZ*NROI)                     // 512 (b,i) pairs

// ---------------- scratch (device globals; no allocation allowed) ----------
__device__ float g_edge[2][(size_t)BSZ*NROI*NROI*HDIM]; // ping-pong edge_state, 2x64MB
__device__ float g_nm[BI*HDIM];                         // nm per layer
__device__ float g_agg[BI*HDIM];                        // agg per layer
__device__ float g_ns[BI*HDIM];                         // node_state
__device__ float g_denom[BI];
__device__ float g_em0[BSZ*HDIM];                       // layer-0 edge matvec result
__device__ float g_e0[BSZ*HDIM];                        // mean of img_featmap

// ---------------- prep: node_state copy, e0 mean, denom --------------------
__global__ void prep_kernel(const float* __restrict__ roi,
                            const float* __restrict__ img,
                            const int*  __restrict__ mask) {
    int idx = blockIdx.x * blockDim.x + threadIdx.x;
    int total = blockDim.x * gridDim.x;
    for (int i = idx; i < BI*HDIM; i += total) g_ns[i] = roi[i];
    if (idx < BSZ*HDIM) {
        const float* p = img + (size_t)idx * 196;
        float s = 0.f;
        #pragma unroll 4
        for (int q = 0; q < 196; q++) s += p[q];
        g_e0[idx] = s * (1.0f/196.0f);
    }
    if (idx < BI) {
        const int* m = mask + idx * NROI;
        int s = 0;
        #pragma unroll
        for (int j = 0; j < NROI; j++) s += m[j];
        g_denom[idx] = (float)s + 1.0f;
    }
}

// ---------------- nm GEMM: g_nm = g_ns @ node_W[t]^T + node_b[t] ------------
// 512x512x512, 64x64 tiles, 256 threads, each thread 4x4 micro-tile.
__global__ void nm_kernel(const float* __restrict__ Wt,
                          const float* __restrict__ bt) {
    __shared__ float As[16][68];
    __shared__ float Ws[16][68];
    int tid = threadIdx.x;
    int tx = tid & 15, ty = tid >> 4;
    int r0 = blockIdx.y * 64, c0 = blockIdx.x * 64;
    const float* A = g_ns + (size_t)r0 * HDIM;
    const float* W = Wt   + (size_t)c0 * HDIM;
    float acc[4][4] = {};
    int lrow = tid >> 2;
    int lk   = (tid & 3) * 4;
    for (int k0 = 0; k0 < HDIM; k0 += 16) {
        float4 a = *(const float4*)(A + (size_t)lrow*HDIM + k0 + lk);
        float4 w = *(const float4*)(W + (size_t)lrow*HDIM + k0 + lk);
        As[lk+0][lrow]=a.x; As[lk+1][lrow]=a.y; As[lk+2][lrow]=a.z; As[lk+3][lrow]=a.w;
        Ws[lk+0][lrow]=w.x; Ws[lk+1][lrow]=w.y; Ws[lk+2][lrow]=w.z; Ws[lk+3][lrow]=w.w;
        __syncthreads();
        #pragma unroll
        for (int k = 0; k < 16; k++) {
            float4 av = *(const float4*)&As[k][ty*4];
            float4 wv = *(const float4*)&Ws[k][tx*4];
            float ar[4] = {av.x, av.y, av.z, av.w};
            float wr[4] = {wv.x, wv.y, wv.z, wv.w};
            #pragma unroll
            for (int r = 0; r < 4; r++)
                #pragma unroll
                for (int c = 0; c < 4; c++)
                    acc[r][c] += ar[r] * wr[c];
        }
        __syncthreads();
    }
    float4 bv = *(const float4*)(bt + c0 + tx*4);
    float bb[4] = {bv.x, bv.y, bv.z, bv.w};
    #pragma unroll
    for (int r = 0; r < 4; r++) {
        int row = r0 + ty*4 + r;
        float4 o;
        o.x = acc[r][0] + bb[0];
        o.y = acc[r][1] + bb[1];
        o.z = acc[r][2] + bb[2];
        o.w = acc[r][3] + bb[3];
        *(float4*)(g_nm + (size_t)row*HDIM + c0 + tx*4) = o;
    }
}

// ---------------- layer-0 edge matvec: em0[b,o] = e0[b,:] . W0[o,:] + eb0[o]
__global__ void em0_kernel(const float* __restrict__ W0,
                           const float* __restrict__ eb0) {
    int warp = (blockIdx.x * blockDim.x + threadIdx.x) >> 5;
    int lane = threadIdx.x & 31;
    if (warp >= BSZ*HDIM) return;
    int b = warp >> 9;
    int o = warp & 511;
    const float* e = g_e0 + b*HDIM;
    const float* w = W0 + (size_t)o*HDIM;
    float s = 0.f;
    for (int h = lane; h < HDIM; h += 32) s += e[h] * w[h];
    #pragma unroll
    for (int d = 16; d; d >>= 1) s += __shfl_xor_sync(0xffffffffu, s, d);
    if (lane == 0) g_em0[warp] = s + eb0[o];
}

// ---------------- fused edge kernel -----------------------------------------
// For one (b,i) and one o-tile of 64:
//   em[j,o] = edge_state[b,i,j,:] . edge_W[t][o,:]   (skipped for t==0, uses em0)
//   e = leaky(nm[b,i,o] + nm[b,j,o] + em + eb)  -> edge_state_next
//   agg[b,i,o] = sum_j e * nm[b,j,o] * mask[b,i,j]
// grid: (8 o-tiles, 512 (b,i)); 256 threads; 4x4 micro-tile over (j, o).
template<bool FIRST>
__global__ void edge_kernel(const float* __restrict__ Wt,
                            const float* __restrict__ ebt,
                            const int*  __restrict__ mask,
                            int src, int dst, int writeEdge) {
    __shared__ float As[16][68];
    __shared__ float Ws[16][68];
    __shared__ float red[16][68];
    int tid = threadIdx.x;
    int tx = tid & 15, ty = tid >> 4;
    int bi = blockIdx.y;           // b*64+i
    int b  = bi >> 6;
    int i  = bi & 63;
    int o0 = blockIdx.x * 64;

    float acc[4][4] = {};
    if (!FIRST) {
        const float* A = g_edge[src] + (size_t)bi * NROI * HDIM;  // [j][h]
        const float* W = Wt + (size_t)o0 * HDIM;                  // [o][h]
        int lrow = tid >> 2;
        int lk   = (tid & 3) * 4;
        for (int k0 = 0; k0 < HDIM; k0 += 16) {
            float4 a = *(const float4*)(A + (size_t)lrow*HDIM + k0 + lk);
            float4 w = *(const float4*)(W + (size_t)lrow*HDIM + k0 + lk);
            As[lk+0][lrow]=a.x; As[lk+1][lrow]=a.y; As[lk+2][lrow]=a.z; As[lk+3][lrow]=a.w;
            Ws[lk+0][lrow]=w.x; Ws[lk+1][lrow]=w.y; Ws[lk+2][lrow]=w.z; Ws[lk+3][lrow]=w.w;
            __syncthreads();
            #pragma unroll
            for (int k = 0; k < 16; k++) {
                float4 av = *(const float4*)&As[k][ty*4];
                float4 wv = *(const float4*)&Ws[k][tx*4];
                float ar[4] = {av.x, av.y, av.z, av.w};
                float wr[4] = {wv.x, wv.y, wv.z, wv.w};
                #pragma unroll
                for (int r = 0; r < 4; r++)
                    #pragma unroll
                    for (int c = 0; c < 4; c++)
                        acc[r][c] += ar[r] * wr[c];
            }
            __syncthreads();
        }
    }

    // ---- epilogue ----
    const float* nmB = g_nm + (size_t)b * NROI * HDIM;
    float4 ni4 = *(const float4*)(nmB + (size_t)i*HDIM + o0 + tx*4);
    float base[4];
    if (FIRST) {
        float4 e04 = *(const float4*)(g_em0 + (size_t)b*HDIM + o0 + tx*4);
        base[0] = ni4.x + e04.x; base[1] = ni4.y + e04.y;
        base[2] = ni4.z + e04.z; base[3] = ni4.w + e04.w;
    } else {
        float4 eb4 = *(const float4*)(ebt + o0 + tx*4);
        base[0] = ni4.x + eb4.x; base[1] = ni4.y + eb4.y;
        base[2] = ni4.z + eb4.z; base[3] = ni4.w + eb4.w;
    }

    float aggp[4] = {0.f, 0.f, 0.f, 0.f};
    #pragma unroll
    for (int r = 0; r < 4; r++) {
        int j = ty*4 + r;
        float m = (float)mask[bi * NROI + j];
        float4 nj = *(const float4*)(nmB + (size_t)j*HDIM + o0 + tx*4);
        float njr[4] = {nj.x, nj.y, nj.z, nj.w};
        float4 ev;
        float* evp = (float*)&ev;
        #pragma unroll
        for (int c = 0; c < 4; c++) {
            float x = acc[r][c] + base[c] + njr[c];
            float e = (x >= 0.f) ? x : 0.01f * x;
            evp[c] = e;
            aggp[c] += e * njr[c] * m;
        }
        if (writeEdge)
            *(float4*)(g_edge[dst] + ((size_t)bi*NROI + j)*HDIM + o0 + tx*4) = ev;
    }

    // block-local reduction over j (rows) -> agg[b,i, o0..o0+63]
    red[ty][tx*4+0] = aggp[0];
    red[ty][tx*4+1] = aggp[1];
    red[ty][tx*4+2] = aggp[2];
    red[ty][tx*4+3] = aggp[3];
    __syncthreads();
    if (tid < 64) {
        float s = 0.f;
        #pragma unroll
        for (int u = 0; u < 16; u++) s += red[u][tid];
        g_agg[(size_t)bi*HDIM + o0 + tid] = s;
    }
}

// ---------------- node update: ns += leaky((nm+agg)/denom) ------------------
__global__ void node_update_kernel() {
    int idx = blockIdx.x * blockDim.x + threadIdx.x;
    if (idx >= BI*HDIM) return;
    int row = idx >> 9;
    float x = (g_nm[idx] + g_agg[idx]) / g_denom[row];
    float l = (x >= 0.f) ? x : 0.01f * x;
    g_ns[idx] += l;
}

// ---------------- output: concat broadcast of node_state --------------------
__global__ void out_kernel(float* __restrict__ out) {
    size_t f = (size_t)blockIdx.x * blockDim.x + threadIdx.x;
    size_t total4 = (size_t)BSZ*NROI*NROI*1024 / 4;
    if (f >= total4) return;
    size_t flat = f * 4;
    int c = (int)(flat & 1023);
    size_t bij = flat >> 10;
    int j = (int)(bij & 63);
    size_t bi = bij >> 6;            // b*64+i
    size_t b  = bi >> 6;
    const float* src = (c < 512)
        ? (g_ns + bi * HDIM + c)
        : (g_ns + (b*64 + j) * HDIM + (c - 512));
    *(float4*)(out + flat) = *(const float4*)src;
}

// ---------------- host launch ------------------------------------------------
extern "C" void kernel_launch(void* const* d_in, const int* in_sizes, int n_in,
                              void* d_out, int out_size) {
    const float* roi = (const float*)d_in[0];
    const float* img = (const float*)d_in[1];
    const float* nW  = (const float*)d_in[2];
    const float* nb  = (const float*)d_in[3];
    const float* eW  = (const float*)d_in[4];
    const float* eb  = (const float*)d_in[5];
    const int*   msk = (const int*)d_in[6];
    float* out = (float*)d_out;

    prep_kernel<<<512, 256>>>(roi, img, msk);

    for (int t = 0; t < NLAYER; t++) {
        nm_kernel<<<dim3(8, 8), 256>>>(nW + (size_t)t*HDIM*HDIM, nb + (size_t)t*HDIM);
        if (t == 0) {
            em0_kernel<<<512, 256>>>(eW, eb);
            edge_kernel<true><<<dim3(8, 512), 256>>>(nullptr, eb, msk, 0, 0, 1);
        } else {
            int dst = t & 1;
            int src = dst ^ 1;
            int we  = (t < NLAYER - 1) ? 1 : 0;   // last layer's edge_state unused
            edge_kernel<false><<<dim3(8, 512), 256>>>(
                eW + (size_t)t*HDIM*HDIM, eb + (size_t)t*HDIM, msk, src, dst, we);
        }
        node_update_kernel<<<1024, 256>>>();
    }

    out_kernel<<<32768, 256>>>(out);
}

// round 3
// speedup vs baseline: 2.9493x; 2.9493x over previous
#include <cuda_runtime.h>
#include <cuda_bf16.h>
#include <cstdint>

#define BSZ   8
#define NROI  64
#define HDIM  512
#define NLAYER 5
#define BI    (BSZ*NROI)                     // 512 (b,i) pairs

// ---------------- scratch (device globals; no allocation allowed) ----------
__device__ __nv_bfloat16 g_ebuf[2][(size_t)BSZ*NROI*NROI*HDIM]; // ping-pong edge_state (bf16), 2x32MB
__device__ __nv_bfloat16 g_eW16[(size_t)NLAYER*HDIM*HDIM];      // bf16 edge weights
__device__ float g_nm[BI*HDIM];
__device__ float g_agg[BI*HDIM];
__device__ float g_ns[BI*HDIM];
__device__ float g_denom[BI];
__device__ float g_em0[BSZ*HDIM];                       // layer-0 edge matvec (incl. bias)
__device__ float g_e0[BSZ*HDIM];                        // mean of img_featmap

__device__ __forceinline__ float leaky(float x) { return x >= 0.f ? x : 0.01f * x; }
__device__ __forceinline__ unsigned smem_u32(const void* p) {
    return (unsigned)__cvta_generic_to_shared(p);
}

// ---------------- prep: node_state copy, e0 mean, denom --------------------
__global__ void prep_kernel(const float* __restrict__ roi,
                            const float* __restrict__ img,
                            const int*  __restrict__ mask) {
    int idx = blockIdx.x * blockDim.x + threadIdx.x;
    int total = blockDim.x * gridDim.x;
    for (int i = idx; i < BI*HDIM; i += total) g_ns[i] = roi[i];
    if (idx < BSZ*HDIM) {
        const float* p = img + (size_t)idx * 196;
        float s = 0.f;
        #pragma unroll 4
        for (int q = 0; q < 196; q++) s += p[q];
        g_e0[idx] = s * (1.0f/196.0f);
    }
    if (idx < BI) {
        const int* m = mask + idx * NROI;
        int s = 0;
        #pragma unroll
        for (int j = 0; j < NROI; j++) s += m[j];
        g_denom[idx] = (float)s + 1.0f;
    }
}

// ---------------- convert edge weights to bf16 once -------------------------
__global__ void convW_kernel(const float* __restrict__ eW) {
    int i = blockIdx.x * blockDim.x + threadIdx.x;
    if (i < NLAYER*HDIM*HDIM) g_eW16[i] = __float2bfloat16(eW[i]);
}

// ---------------- nm GEMM: g_nm = g_ns @ node_W[t]^T + node_b[t] (fp32) -----
__global__ void nm_kernel(const float* __restrict__ Wt,
                          const float* __restrict__ bt) {
    __shared__ float As[16][68];
    __shared__ float Ws[16][68];
    int tid = threadIdx.x;
    int tx = tid & 15, ty = tid >> 4;
    int r0 = blockIdx.y * 64, c0 = blockIdx.x * 64;
    const float* A = g_ns + (size_t)r0 * HDIM;
    const float* W = Wt   + (size_t)c0 * HDIM;
    float acc[4][4] = {};
    int lrow = tid >> 2;
    int lk   = (tid & 3) * 4;
    for (int k0 = 0; k0 < HDIM; k0 += 16) {
        float4 a = *(const float4*)(A + (size_t)lrow*HDIM + k0 + lk);
        float4 w = *(const float4*)(W + (size_t)lrow*HDIM + k0 + lk);
        As[lk+0][lrow]=a.x; As[lk+1][lrow]=a.y; As[lk+2][lrow]=a.z; As[lk+3][lrow]=a.w;
        Ws[lk+0][lrow]=w.x; Ws[lk+1][lrow]=w.y; Ws[lk+2][lrow]=w.z; Ws[lk+3][lrow]=w.w;
        __syncthreads();
        #pragma unroll
        for (int k = 0; k < 16; k++) {
            float4 av = *(const float4*)&As[k][ty*4];
            float4 wv = *(const float4*)&Ws[k][tx*4];
            float ar[4] = {av.x, av.y, av.z, av.w};
            float wr[4] = {wv.x, wv.y, wv.z, wv.w};
            #pragma unroll
            for (int r = 0; r < 4; r++)
                #pragma unroll
                for (int c = 0; c < 4; c++)
                    acc[r][c] += ar[r] * wr[c];
        }
        __syncthreads();
    }
    float4 bv = *(const float4*)(bt + c0 + tx*4);
    float bb[4] = {bv.x, bv.y, bv.z, bv.w};
    #pragma unroll
    for (int r = 0; r < 4; r++) {
        int row = r0 + ty*4 + r;
        float4 o;
        o.x = acc[r][0] + bb[0];
        o.y = acc[r][1] + bb[1];
        o.z = acc[r][2] + bb[2];
        o.w = acc[r][3] + bb[3];
        *(float4*)(g_nm + (size_t)row*HDIM + c0 + tx*4) = o;
    }
}

// ---------------- layer-0 edge matvec: em0[b,o] = e0[b,:] . W0[o,:] + eb0[o]
__global__ void em0_kernel(const float* __restrict__ W0,
                           const float* __restrict__ eb0) {
    int warp = (blockIdx.x * blockDim.x + threadIdx.x) >> 5;
    int lane = threadIdx.x & 31;
    if (warp >= BSZ*HDIM) return;
    int b = warp >> 9;
    int o = warp & 511;
    const float* e = g_e0 + b*HDIM;
    const float* w = W0 + (size_t)o*HDIM;
    float s = 0.f;
    for (int h = lane; h < HDIM; h += 32) s += e[h] * w[h];
    #pragma unroll
    for (int d = 16; d; d >>= 1) s += __shfl_xor_sync(0xffffffffu, s, d);
    if (lane == 0) g_em0[warp] = s + eb0[o];
}

// ---------------- layer-0 fused edge (no GEMM): writes bf16 edge_state ------
__global__ void edge0_kernel(const int* __restrict__ mask) {
    int bi = blockIdx.x;
    int b  = bi >> 6;
    const float* nmB = g_nm + (size_t)b * NROI * HDIM;
    const float* nmi = g_nm + (size_t)bi * HDIM;
    __nv_bfloat16* dstp = g_ebuf[0] + (size_t)bi * NROI * HDIM;
    int o1 = threadIdx.x, o2 = threadIdx.x + 256;
    float base1 = nmi[o1] + g_em0[b*HDIM + o1];
    float base2 = nmi[o2] + g_em0[b*HDIM + o2];
    float agg1 = 0.f, agg2 = 0.f;
    for (int j = 0; j < NROI; j++) {
        float m = (float)mask[bi*NROI + j];
        float nj1 = nmB[j*HDIM + o1];
        float nj2 = nmB[j*HDIM + o2];
        float e1 = leaky(base1 + nj1);
        float e2 = leaky(base2 + nj2);
        dstp[j*HDIM + o1] = __float2bfloat16(e1);
        dstp[j*HDIM + o2] = __float2bfloat16(e2);
        agg1 += e1 * nj1 * m;
        agg2 += e2 * nj2 * m;
    }
    g_agg[(size_t)bi*HDIM + o1] = agg1;
    g_agg[(size_t)bi*HDIM + o2] = agg2;
}

// ---------------- fused edge GEMM (layers 1..4), bf16 tensor cores ----------
// Block: one (b,i), o-tile of 128. GEMM 64(j) x 128(o) x 512(k), bf16 HMMA,
// fp32 accum. Fused epilogue: leaky + bf16 edge write + masked agg reduction.
// NOTE: weight pointer computed IN-KERNEL from layer index t (device symbol
// address is invalid host-side).
__global__ __launch_bounds__(256) void edge_mma_kernel(
    int t,                                   // layer index (selects weight slice)
    const float* __restrict__ ebt,
    const int*  __restrict__ mask,
    int src, int dst, int writeEdge)
{
    __shared__ __nv_bfloat16 As[64*72];
    __shared__ __nv_bfloat16 Bs[128*72];
    __shared__ float aggsm[4][128];

    int tid  = threadIdx.x;
    int wid  = tid >> 5, lane = tid & 31;
    int wm   = wid & 3;        // 4 warps over m (j)
    int wn   = wid >> 2;       // 2 warps over n (o)
    int bi   = blockIdx.y;
    int b    = bi >> 6;
    int o0   = blockIdx.x * 128;

    const __nv_bfloat16* W16 = g_eW16 + (size_t)t * HDIM * HDIM;
    const __nv_bfloat16* A = g_ebuf[src] + (size_t)bi * NROI * HDIM; // [j][k]
    const __nv_bfloat16* Bw = W16 + (size_t)o0 * HDIM;               // [o][k]

    float acc[8][4] = {};     // 8 n-frags x 4 accum regs

    // global->smem load indices (64-wide k chunks)
    int arow = tid >> 2, acol = (tid & 3) * 16;   // A: 64 rows x 64 k
    int brow = tid >> 1, bcol = (tid & 1) * 32;   // B: 128 rows x 64 k

    // ldmatrix base addresses
    unsigned aBase = smem_u32(As + (wm*16 + (lane & 15))*72 + (lane >> 4)*8);
    unsigned bBase = smem_u32(Bs + (wn*64 + ((lane >> 4) << 3) + (lane & 7))*72
                                 + (((lane >> 3) & 1) << 3));

    for (int k0 = 0; k0 < HDIM; k0 += 64) {
        *(uint4*)(As + arow*72 + acol)     = *(const uint4*)(A + (size_t)arow*HDIM + k0 + acol);
        *(uint4*)(As + arow*72 + acol + 8) = *(const uint4*)(A + (size_t)arow*HDIM + k0 + acol + 8);
        #pragma unroll
        for (int q = 0; q < 4; q++)
            *(uint4*)(Bs + brow*72 + bcol + q*8) =
                *(const uint4*)(Bw + (size_t)brow*HDIM + k0 + bcol + q*8);
        __syncthreads();

        #pragma unroll
        for (int ks = 0; ks < 64; ks += 16) {
            unsigned a0,a1,a2,a3;
            asm volatile("ldmatrix.sync.aligned.m8n8.x4.shared.b16 {%0,%1,%2,%3},[%4];"
                : "=r"(a0),"=r"(a1),"=r"(a2),"=r"(a3) : "r"(aBase + (unsigned)(ks*2)));
            #pragma unroll
            for (int p2 = 0; p2 < 4; p2++) {
                unsigned bAddr = bBase + (unsigned)((p2*16*72 + ks) * 2);
                unsigned b0,b1,b2,b3;
                asm volatile("ldmatrix.sync.aligned.m8n8.x4.shared.b16 {%0,%1,%2,%3},[%4];"
                    : "=r"(b0),"=r"(b1),"=r"(b2),"=r"(b3) : "r"(bAddr));
                float* c0 = acc[p2*2];
                asm volatile("mma.sync.aligned.m16n8k16.row.col.f32.bf16.bf16.f32 "
                    "{%0,%1,%2,%3},{%4,%5,%6,%7},{%8,%9},{%0,%1,%2,%3};"
                    : "+f"(c0[0]),"+f"(c0[1]),"+f"(c0[2]),"+f"(c0[3])
                    : "r"(a0),"r"(a1),"r"(a2),"r"(a3),"r"(b0),"r"(b1));
                float* c1 = acc[p2*2+1];
                asm volatile("mma.sync.aligned.m16n8k16.row.col.f32.bf16.bf16.f32 "
                    "{%0,%1,%2,%3},{%4,%5,%6,%7},{%8,%9},{%0,%1,%2,%3};"
                    : "+f"(c1[0]),"+f"(c1[1]),"+f"(c1[2]),"+f"(c1[3])
                    : "r"(a0),"r"(a1),"r"(a2),"r"(a3),"r"(b2),"r"(b3));
            }
        }
        __syncthreads();
    }

    // ---- fused epilogue ----
    const float* nmB = g_nm + (size_t)b * NROI * HDIM;
    int rbase = wm*16 + (lane >> 2);
    int j1 = rbase, j2 = rbase + 8;
    float m1 = (float)mask[bi*NROI + j1];
    float m2 = (float)mask[bi*NROI + j2];
    __nv_bfloat16* dstp = g_ebuf[dst] + (size_t)bi * NROI * HDIM;

    #pragma unroll
    for (int p = 0; p < 8; p++) {
        int o = o0 + wn*64 + p*8 + (lane & 3)*2;
        float2 ni  = *(const float2*)(g_nm + (size_t)bi*HDIM + o);
        float2 ebv = *(const float2*)(ebt + o);
        float2 nj1 = *(const float2*)(nmB + (size_t)j1*HDIM + o);
        float2 nj2 = *(const float2*)(nmB + (size_t)j2*HDIM + o);
        float bx = ni.x + ebv.x, by = ni.y + ebv.y;
        float e00 = leaky(acc[p][0] + bx + nj1.x);
        float e01 = leaky(acc[p][1] + by + nj1.y);
        float e10 = leaky(acc[p][2] + bx + nj2.x);
        float e11 = leaky(acc[p][3] + by + nj2.y);
        if (writeEdge) {
            __nv_bfloat162 v1; v1.x = __float2bfloat16(e00); v1.y = __float2bfloat16(e01);
            __nv_bfloat162 v2; v2.x = __float2bfloat16(e10); v2.y = __float2bfloat16(e11);
            *(__nv_bfloat162*)(dstp + (size_t)j1*HDIM + o) = v1;
            *(__nv_bfloat162*)(dstp + (size_t)j2*HDIM + o) = v2;
        }
        float s0 = e00*nj1.x*m1 + e10*nj2.x*m2;
        float s1 = e01*nj1.y*m1 + e11*nj2.y*m2;
        #pragma unroll
        for (int d = 4; d <= 16; d <<= 1) {
            s0 += __shfl_xor_sync(0xffffffffu, s0, d);
            s1 += __shfl_xor_sync(0xffffffffu, s1, d);
        }
        if (lane < 4) {
            int oc = wn*64 + p*8 + lane*2;
            aggsm[wm][oc]   = s0;
            aggsm[wm][oc+1] = s1;
        }
    }
    __syncthreads();
    if (tid < 128) {
        float s = aggsm[0][tid] + aggsm[1][tid] + aggsm[2][tid] + aggsm[3][tid];
        g_agg[(size_t)bi*HDIM + o0 + tid] = s;
    }
}

// ---------------- node update: ns += leaky((nm+agg)/denom) ------------------
__global__ void node_update_kernel() {
    int idx = blockIdx.x * blockDim.x + threadIdx.x;
    if (idx >= BI*HDIM) return;
    int row = idx >> 9;
    float x = (g_nm[idx] + g_agg[idx]) / g_denom[row];
    g_ns[idx] += leaky(x);
}

// ---------------- output: concat broadcast of node_state --------------------
__global__ void out_kernel(float* __restrict__ out) {
    size_t f = (size_t)blockIdx.x * blockDim.x + threadIdx.x;
    size_t total4 = (size_t)BSZ*NROI*NROI*1024 / 4;
    if (f >= total4) return;
    size_t flat = f * 4;
    int c = (int)(flat & 1023);
    size_t bij = flat >> 10;
    int j = (int)(bij & 63);
    size_t bi = bij >> 6;            // b*64+i
    size_t b  = bi >> 6;
    const float* src = (c < 512)
        ? (g_ns + bi * HDIM + c)
        : (g_ns + (b*64 + j) * HDIM + (c - 512));
    *(float4*)(out + flat) = *(const float4*)src;
}

// ---------------- host launch ------------------------------------------------
extern "C" void kernel_launch(void* const* d_in, const int* in_sizes, int n_in,
                              void* d_out, int out_size) {
    const float* roi = (const float*)d_in[0];
    const float* img = (const float*)d_in[1];
    const float* nW  = (const float*)d_in[2];
    const float* nb  = (const float*)d_in[3];
    const float* eW  = (const float*)d_in[4];
    const float* eb  = (const float*)d_in[5];
    const int*   msk = (const int*)d_in[6];
    float* out = (float*)d_out;

    prep_kernel<<<512, 256>>>(roi, img, msk);
    convW_kernel<<<(NLAYER*HDIM*HDIM + 255)/256, 256>>>(eW);

    for (int t = 0; t < NLAYER; t++) {
        nm_kernel<<<dim3(8, 8), 256>>>(nW + (size_t)t*HDIM*HDIM, nb + (size_t)t*HDIM);
        if (t == 0) {
            em0_kernel<<<512, 256>>>(eW, eb);
            edge0_kernel<<<512, 256>>>(msk);
        } else {
            int dst = t & 1;
            int src = dst ^ 1;
            int we  = (t < NLAYER - 1) ? 1 : 0;   // last layer's edge_state unused
            edge_mma_kernel<<<dim3(4, 512), 256>>>(
                t, eb + (size_t)t*HDIM, msk, src, dst, we);
        }
        node_update_kernel<<<1024, 256>>>();
    }

    out_kernel<<<32768, 256>>>(out);
}